// round 6
// baseline (speedup 1.0000x reference)
#include <cuda_runtime.h>
#include <cuda_bf16.h>
#include <math_constants.h>

// Problem constants
#define NB 8          // batch
#define NY 180        // RENDER
#define NX 91         // XDIM+1
#define NV 192        // TEMPLATERES
#define SCALE_IN (32400.0f / 7077888.0f)   // RENDER^2 / TEMPLATERES^3

// Scratch (device globals; no allocation allowed)
__device__ float2 g_cross[NB * NY * NX];   // after sample * conj(ref), fftshifted
__device__ float2 g_tmid[NB * NY * NX];    // after iDFT along y:  [b][ky][x]
__device__ float  g_r[NB * NY * NY];       // real correlation map [b][ky][m]

// ---------------------------------------------------------------------------
// Kernel 1: rotate grid, trilinear-sample volume (zero pad), * conj(ref).
// Output row y is already fftshifted: cross[y] = sc[(y+90)%180] * conj(ref[y])
// ---------------------------------------------------------------------------
__global__ void k_sample_cross(const float* __restrict__ src,
                               const float* __restrict__ rot,
                               const float* __restrict__ ref)
{
    int tid = blockIdx.x * blockDim.x + threadIdx.x;
    if (tid >= NB * NY * NX) return;
    int x = tid % NX;
    int t = tid / NX;
    int y = t % NY;
    int b = t / NY;

    int g = y + 90; if (g >= 180) g -= 180;       // pre-shift grid row index
    float gx = (float)x        * (1.0f / 96.0f);
    float gy = (float)(g - 90) * (1.0f / 96.0f);

    const float* R = rot + b * 9;                  // (3,3) row-major
    // pos = [gx,gy,0] @ R
    float p0 = gx * R[0] + gy * R[3];
    float p1 = gx * R[1] + gy * R[4];
    float p2 = gx * R[2] + gy * R[5];

    float fx = (p0 + 1.0f) * 0.5f * 191.0f;
    float fy = (p1 + 1.0f) * 0.5f * 191.0f;
    float fz = (p2 + 1.0f) * 0.5f * 191.0f;
    float fx0 = floorf(fx), fy0 = floorf(fy), fz0 = floorf(fz);
    float wx = fx - fx0, wy = fy - fy0, wz = fz - fz0;
    int x0 = (int)fx0, y0 = (int)fy0, z0 = (int)fz0;

    const float* vr = src + (size_t)b * 2 * NV * NV * NV;
    const float* vi = vr + (size_t)NV * NV * NV;

    float re = 0.0f, im = 0.0f;
#pragma unroll
    for (int dz = 0; dz < 2; dz++) {
        int zi = z0 + dz;
        if ((unsigned)zi >= NV) continue;
        float wzc = dz ? wz : 1.0f - wz;
#pragma unroll
        for (int dy = 0; dy < 2; dy++) {
            int yi = y0 + dy;
            if ((unsigned)yi >= NV) continue;
            float wyc = dy ? wy : 1.0f - wy;
#pragma unroll
            for (int dx = 0; dx < 2; dx++) {
                int xi = x0 + dx;
                if ((unsigned)xi >= NV) continue;
                float wxc = dx ? wx : 1.0f - wx;
                float w = wzc * wyc * wxc;
                size_t idx = ((size_t)zi * NV + yi) * NV + xi;
                re += w * __ldg(vr + idx);
                im += w * __ldg(vi + idx);
            }
        }
    }
    re *= SCALE_IN;
    im *= SCALE_IN;

    const float* rp = ref + ((size_t)(b * NY + y) * NX + x) * 2;
    float rr = rp[0], ri = rp[1];
    // sc * conj(ref)
    g_cross[tid] = make_float2(re * rr + im * ri, im * rr - re * ri);
}

// ---------------------------------------------------------------------------
// Kernel 2: inverse DFT along y (length 180) per (b, x) column.
// t[ky] = sum_y cross[y] * e^{+2*pi*i*y*ky/180}   (1/N folded into kernel 3)
// ---------------------------------------------------------------------------
__global__ void k_ifft_y()
{
    __shared__ float2 col[NY];
    __shared__ float2 tw[NY];
    int bx = blockIdx.x;          // 0 .. NB*NX-1
    int x  = bx % NX;
    int b  = bx / NX;
    int t  = threadIdx.x;

    if (t < NY) {
        float s, c;
        sincospif((float)t * (1.0f / 90.0f), &s, &c);   // angle = 2*pi*t/180
        tw[t]  = make_float2(c, s);
        col[t] = g_cross[(b * NY + t) * NX + x];
    }
    __syncthreads();

    if (t < NY) {
        int ky = t;
        float ar = 0.0f, ai = 0.0f;
        int idx = 0;
        for (int y = 0; y < NY; y++) {
            float2 c = col[y];
            float2 w = tw[idx];
            ar += c.x * w.x - c.y * w.y;
            ai += c.x * w.y + c.y * w.x;
            idx += ky; if (idx >= NY) idx -= NY;
        }
        g_tmid[(b * NY + ky) * NX + x] = make_float2(ar, ai);
    }
}

// ---------------------------------------------------------------------------
// Kernel 3: c2r inverse DFT along x (91 -> 180) per (b, ky) row.
// r[m] = (1/180^2) * ( Re a0 + (-1)^m * Re a90
//                      + 2 * sum_{k=1}^{89} Re{ a_k e^{+2*pi*i*k*m/180} } )
// Output pre-multiplied by 2 (final r_k_val factor); positive scale keeps
// the top-k ordering identical.
// ---------------------------------------------------------------------------
__global__ void k_c2r_x()
{
    __shared__ float2 row[NX];
    __shared__ float2 tw[NY];
    int bx = blockIdx.x;          // 0 .. NB*NY-1
    int ky = bx % NY;
    int b  = bx / NY;
    int t  = threadIdx.x;

    if (t < NY) {
        float s, c;
        sincospif((float)t * (1.0f / 90.0f), &s, &c);
        tw[t] = make_float2(c, s);
    }
    if (t < NX) row[t] = g_tmid[(b * NY + ky) * NX + t];
    __syncthreads();

    if (t < NY) {
        int m = t;
        float acc = row[0].x + ((m & 1) ? -row[90].x : row[90].x);
        float s2 = 0.0f;
        int idx = m;              // k=1 term: (1*m) % 180 == m
        for (int k = 1; k < 90; k++) {
            float2 w = tw[idx];
            float2 c = row[k];
            s2 += c.x * w.x - c.y * w.y;
            idx += m; if (idx >= NY) idx -= NY;
        }
        acc += 2.0f * s2;
        // factor: 2 (r_k_val) / (180*180) (irfft2 norm)
        g_r[(b * NY + ky) * NY + m] = acc * (2.0f / 32400.0f);
    }
}

// ---------------------------------------------------------------------------
// Kernel 4: per-batch top-4 (value desc, ties -> lower index) + output pack.
// Output layout: [0,32)   r_k_val (8,4)
//                [32,96)  trans   (8,4,2)  = (ind%180-90, ind/180-90)
// ---------------------------------------------------------------------------
__global__ void k_topk(float* __restrict__ out)
{
    const int T = 256;
    __shared__ float sv[T * 4];
    __shared__ int   si[T * 4];
    int b = blockIdx.x;
    int t = threadIdx.x;

    float lv[4] = { -CUDART_INF_F, -CUDART_INF_F, -CUDART_INF_F, -CUDART_INF_F };
    int   li[4] = { 0x7fffffff, 0x7fffffff, 0x7fffffff, 0x7fffffff };

    const float* r = g_r + (size_t)b * NY * NY;
    for (int i = t; i < NY * NY; i += T) {
        float v = r[i];
        if (v > lv[3] || (v == lv[3] && i < li[3])) {
            int j = 3;
            while (j > 0 && (v > lv[j - 1] || (v == lv[j - 1] && i < li[j - 1]))) {
                lv[j] = lv[j - 1]; li[j] = li[j - 1]; j--;
            }
            lv[j] = v; li[j] = i;
        }
    }
#pragma unroll
    for (int k = 0; k < 4; k++) { sv[t * 4 + k] = lv[k]; si[t * 4 + k] = li[k]; }
    __syncthreads();

    for (int s = T / 2; s > 0; s >>= 1) {
        if (t < s) {
            float av[4]; int ai[4];
            int p = 0, q = 0;
#pragma unroll
            for (int k = 0; k < 4; k++) {
                float v1 = (p < 4) ? sv[t * 4 + p]       : -CUDART_INF_F;
                int   i1 = (p < 4) ? si[t * 4 + p]       : 0x7fffffff;
                float v2 = (q < 4) ? sv[(t + s) * 4 + q] : -CUDART_INF_F;
                int   i2 = (q < 4) ? si[(t + s) * 4 + q] : 0x7fffffff;
                bool take1 = (v1 > v2) || (v1 == v2 && i1 < i2);
                if (take1) { av[k] = v1; ai[k] = i1; p++; }
                else       { av[k] = v2; ai[k] = i2; q++; }
            }
#pragma unroll
            for (int k = 0; k < 4; k++) { sv[t * 4 + k] = av[k]; si[t * 4 + k] = ai[k]; }
        }
        __syncthreads();
    }

    if (t == 0) {
#pragma unroll
        for (int k = 0; k < 4; k++) {
            float v = sv[k];
            int idx = si[k];
            out[b * 4 + k] = v;                         // already includes *2
            int m  = idx % NY;
            int yy = idx / NY;
            out[32 + (b * 4 + k) * 2 + 0] = (float)(m  - 90);
            out[32 + (b * 4 + k) * 2 + 1] = (float)(yy - 90);
        }
    }
}

// ---------------------------------------------------------------------------
extern "C" void kernel_launch(void* const* d_in, const int* in_sizes, int n_in,
                              void* d_out, int out_size)
{
    // Positional defaults per metadata order: src, rot, ref_fft, gridF
    const float* src = (const float*)d_in[0];   // 8*2*192^3 = 113246208
    const float* rot = (n_in > 1) ? (const float*)d_in[1] : nullptr;  // 72
    const float* ref = (n_in > 2) ? (const float*)d_in[2] : nullptr;  // 262080
    // Defensive remap by element count (overrides positional if sizes match)
    for (int i = 0; i < n_in; i++) {
        switch (in_sizes[i]) {
            case 113246208: src = (const float*)d_in[i]; break;
            case 72:        rot = (const float*)d_in[i]; break;
            case 262080:    ref = (const float*)d_in[i]; break;
            default: break; // gridF (49413) unused — recomputed analytically
        }
    }
    float* out = (float*)d_out;

    k_sample_cross<<<(NB * NY * NX + 255) / 256, 256>>>(src, rot, ref);
    k_ifft_y<<<NB * NX, 192>>>();
    k_c2r_x<<<NB * NY, 192>>>();
    k_topk<<<NB, 256>>>(out);
}

// round 8
// speedup vs baseline: 1.8762x; 1.8762x over previous
#include <cuda_runtime.h>
#include <cuda_bf16.h>
#include <math_constants.h>

// Problem constants
#define NB 8          // batch
#define NY 180        // RENDER
#define NX 91         // XDIM+1
#define NV 192        // TEMPLATERES
#define SCALE_IN (32400.0f / 7077888.0f)   // RENDER^2 / TEMPLATERES^3

typedef unsigned long long ull;

// Scratch (device globals; no allocation allowed)
__device__ float2 g_cross[NB * NY * NX];   // after sample * conj(ref), fftshifted
__device__ float2 g_tmid[NB * NY * NX];    // after iDFT along y:  [b][ky][x]
__device__ ull    g_cand[NB * NY * 4];     // per-row top-4 packed keys

// ---- packed key helpers: (orderable float bits << 32) | ~index -------------
__device__ __forceinline__ unsigned f2ord(float v) {
    unsigned u = __float_as_uint(v);
    return (u & 0x80000000u) ? ~u : (u | 0x80000000u);
}
__device__ __forceinline__ float ord2f(unsigned ou) {
    unsigned u = (ou & 0x80000000u) ? (ou ^ 0x80000000u) : ~ou;
    return __uint_as_float(u);
}
__device__ __forceinline__ ull umax(ull a, ull b) { return a > b ? a : b; }
__device__ __forceinline__ ull umin(ull a, ull b) { return a < b ? a : b; }

// Branch-free merge of two desc-sorted 4-lists -> top-4 (keys are unique).
// merged[k] = max over {a_k, b_k, min(a_i,b_j) : i+j=k-1}
__device__ __forceinline__ void merge4(ull& a0, ull& a1, ull& a2, ull& a3,
                                       ull b0, ull b1, ull b2, ull b3) {
    ull m0 = umax(a0, b0);
    ull m1 = umax(umax(a1, b1), umin(a0, b0));
    ull m2 = umax(umax(a2, b2), umax(umin(a0, b1), umin(a1, b0)));
    ull m3 = umax(umax(a3, b3),
                  umax(umin(a1, b1), umax(umin(a0, b2), umin(a2, b0))));
    a0 = m0; a1 = m1; a2 = m2; a3 = m3;
}

// ---------------------------------------------------------------------------
// Kernel 1: rotate grid, trilinear-sample volume (zero pad), * conj(ref).
// Output row y is already fftshifted: cross[y] = sc[(y+90)%180] * conj(ref[y])
// ---------------------------------------------------------------------------
__global__ void k_sample_cross(const float* __restrict__ src,
                               const float* __restrict__ rot,
                               const float* __restrict__ ref)
{
    int tid = blockIdx.x * blockDim.x + threadIdx.x;
    if (tid >= NB * NY * NX) return;
    int x = tid % NX;
    int t = tid / NX;
    int y = t % NY;
    int b = t / NY;

    int g = y + 90; if (g >= 180) g -= 180;       // pre-shift grid row index
    float gx = (float)x        * (1.0f / 96.0f);
    float gy = (float)(g - 90) * (1.0f / 96.0f);

    const float* R = rot + b * 9;                  // (3,3) row-major
    float p0 = gx * R[0] + gy * R[3];
    float p1 = gx * R[1] + gy * R[4];
    float p2 = gx * R[2] + gy * R[5];

    float fx = (p0 + 1.0f) * 0.5f * 191.0f;
    float fy = (p1 + 1.0f) * 0.5f * 191.0f;
    float fz = (p2 + 1.0f) * 0.5f * 191.0f;
    float fx0 = floorf(fx), fy0 = floorf(fy), fz0 = floorf(fz);
    float wx = fx - fx0, wy = fy - fy0, wz = fz - fz0;
    int x0 = (int)fx0, y0 = (int)fy0, z0 = (int)fz0;

    const float* vr = src + (size_t)b * 2 * NV * NV * NV;
    const float* vi = vr + (size_t)NV * NV * NV;

    float re = 0.0f, im = 0.0f;
#pragma unroll
    for (int dz = 0; dz < 2; dz++) {
        int zi = z0 + dz;
        if ((unsigned)zi >= NV) continue;
        float wzc = dz ? wz : 1.0f - wz;
#pragma unroll
        for (int dy = 0; dy < 2; dy++) {
            int yi = y0 + dy;
            if ((unsigned)yi >= NV) continue;
            float wyc = dy ? wy : 1.0f - wy;
#pragma unroll
            for (int dx = 0; dx < 2; dx++) {
                int xi = x0 + dx;
                if ((unsigned)xi >= NV) continue;
                float wxc = dx ? wx : 1.0f - wx;
                float w = wzc * wyc * wxc;
                size_t idx = ((size_t)zi * NV + yi) * NV + xi;
                re += w * __ldg(vr + idx);
                im += w * __ldg(vi + idx);
            }
        }
    }
    re *= SCALE_IN;
    im *= SCALE_IN;

    const float* rp = ref + ((size_t)(b * NY + y) * NX + x) * 2;
    float rr = rp[0], ri = rp[1];
    g_cross[tid] = make_float2(re * rr + im * ri, im * rr - re * ri);
}

// ---------------------------------------------------------------------------
// Kernel 2: inverse DFT along y (length 180) per (b, x) column.
// ---------------------------------------------------------------------------
__global__ void k_ifft_y()
{
    __shared__ float2 col[NY];
    __shared__ float2 tw[NY];
    int bx = blockIdx.x;          // 0 .. NB*NX-1
    int x  = bx % NX;
    int b  = bx / NX;
    int t  = threadIdx.x;

    if (t < NY) {
        float s, c;
        sincospif((float)t * (1.0f / 90.0f), &s, &c);   // 2*pi*t/180
        tw[t]  = make_float2(c, s);
        col[t] = g_cross[(b * NY + t) * NX + x];
    }
    __syncthreads();

    if (t < NY) {
        int ky = t;
        float ar = 0.0f, ai = 0.0f;
        int idx = 0;
        for (int y = 0; y < NY; y++) {
            float2 c = col[y];
            float2 w = tw[idx];
            ar += c.x * w.x - c.y * w.y;
            ai += c.x * w.y + c.y * w.x;
            idx += ky; if (idx >= NY) idx -= NY;
        }
        g_tmid[(b * NY + ky) * NX + x] = make_float2(ar, ai);
    }
}

// ---------------------------------------------------------------------------
// Kernel 3: c2r inverse DFT along x (91 -> 180) per (b, ky) row, FUSED with
// per-row top-4 reduction (packed-key warp reduce). Emits 4 candidate keys
// per row into g_cand; no full correlation map ever hits global memory.
// ---------------------------------------------------------------------------
__global__ void k_c2r_x_top4()
{
    __shared__ float2 row[NX];
    __shared__ float2 tw[NY];
    __shared__ ull    wtop[6][4];
    int bx = blockIdx.x;          // 0 .. NB*NY-1
    int ky = bx % NY;
    int b  = bx / NY;
    int t  = threadIdx.x;         // 0..191 (6 full warps)

    if (t < NY) {
        float s, c;
        sincospif((float)t * (1.0f / 90.0f), &s, &c);
        tw[t] = make_float2(c, s);
    }
    if (t < NX) row[t] = g_tmid[(b * NY + ky) * NX + t];
    __syncthreads();

    ull key = 0;                  // neutral (below any real key)
    if (t < NY) {
        int m = t;
        float acc = row[0].x + ((m & 1) ? -row[90].x : row[90].x);
        float s2 = 0.0f;
        int idx = m;
        for (int k = 1; k < 90; k++) {
            float2 w = tw[idx];
            float2 c = row[k];
            s2 += c.x * w.x - c.y * w.y;
            idx += m; if (idx >= NY) idx -= NY;
        }
        acc += 2.0f * s2;
        float val = acc * (2.0f / 32400.0f);  // 2 (r_k_val) / 180^2 (irfft2)
        unsigned gi = (unsigned)(ky * NY + m);
        key = ((ull)f2ord(val) << 32) | (unsigned)(~gi);
    }

    // warp-level top-4 (all 32 lanes active; keys unique except neutral 0)
    ull a0 = key, a1 = 0, a2 = 0, a3 = 0;
#pragma unroll
    for (int s = 16; s > 0; s >>= 1) {
        ull b0 = __shfl_xor_sync(0xFFFFFFFFu, a0, s);
        ull b1 = __shfl_xor_sync(0xFFFFFFFFu, a1, s);
        ull b2 = __shfl_xor_sync(0xFFFFFFFFu, a2, s);
        ull b3 = __shfl_xor_sync(0xFFFFFFFFu, a3, s);
        merge4(a0, a1, a2, a3, b0, b1, b2, b3);
    }
    int wid = t >> 5, lane = t & 31;
    if (lane == 0) { wtop[wid][0] = a0; wtop[wid][1] = a1; wtop[wid][2] = a2; wtop[wid][3] = a3; }
    __syncthreads();

    if (t == 0) {
        ull r0 = wtop[0][0], r1 = wtop[0][1], r2 = wtop[0][2], r3 = wtop[0][3];
#pragma unroll
        for (int w = 1; w < 6; w++)
            merge4(r0, r1, r2, r3, wtop[w][0], wtop[w][1], wtop[w][2], wtop[w][3]);
        ull* c = g_cand + (size_t)(b * NY + ky) * 4;
        c[0] = r0; c[1] = r1; c[2] = r2; c[3] = r3;
    }
}

// ---------------------------------------------------------------------------
// Kernel 4: merge 180*4 candidates per batch -> final top-4, unpack, output.
// Output layout: [0,32) r_k_val (8,4); [32,96) trans (8,4,2).
// ---------------------------------------------------------------------------
__global__ void k_final(float* __restrict__ out)
{
    __shared__ ull wtop[6][4];
    int b = blockIdx.x;
    int t = threadIdx.x;          // 0..191
    const ull* cand = g_cand + (size_t)b * NY * 4;

    ull a0 = 0, a1 = 0, a2 = 0, a3 = 0;
#pragma unroll
    for (int j = 0; j < 4; j++) {
        int i = t + j * 192;
        ull x = (i < NY * 4) ? cand[i] : 0;
        merge4(a0, a1, a2, a3, x, 0, 0, 0);
    }
#pragma unroll
    for (int s = 16; s > 0; s >>= 1) {
        ull b0 = __shfl_xor_sync(0xFFFFFFFFu, a0, s);
        ull b1 = __shfl_xor_sync(0xFFFFFFFFu, a1, s);
        ull b2 = __shfl_xor_sync(0xFFFFFFFFu, a2, s);
        ull b3 = __shfl_xor_sync(0xFFFFFFFFu, a3, s);
        merge4(a0, a1, a2, a3, b0, b1, b2, b3);
    }
    int wid = t >> 5, lane = t & 31;
    if (lane == 0) { wtop[wid][0] = a0; wtop[wid][1] = a1; wtop[wid][2] = a2; wtop[wid][3] = a3; }
    __syncthreads();

    if (t == 0) {
        ull r0 = wtop[0][0], r1 = wtop[0][1], r2 = wtop[0][2], r3 = wtop[0][3];
#pragma unroll
        for (int w = 1; w < 6; w++)
            merge4(r0, r1, r2, r3, wtop[w][0], wtop[w][1], wtop[w][2], wtop[w][3]);
        ull rs[4] = { r0, r1, r2, r3 };
#pragma unroll
        for (int k = 0; k < 4; k++) {
            ull key = rs[k];
            float v = ord2f((unsigned)(key >> 32));
            unsigned gi = ~((unsigned)(key & 0xFFFFFFFFu));
            int m  = (int)(gi % NY);
            int yy = (int)(gi / NY);
            out[b * 4 + k] = v;
            out[32 + (b * 4 + k) * 2 + 0] = (float)(m  - 90);
            out[32 + (b * 4 + k) * 2 + 1] = (float)(yy - 90);
        }
    }
}

// ---------------------------------------------------------------------------
extern "C" void kernel_launch(void* const* d_in, const int* in_sizes, int n_in,
                              void* d_out, int out_size)
{
    // Positional defaults per metadata order: src, rot, ref_fft, gridF
    const float* src = (const float*)d_in[0];   // 8*2*192^3 = 113246208
    const float* rot = (n_in > 1) ? (const float*)d_in[1] : nullptr;  // 72
    const float* ref = (n_in > 2) ? (const float*)d_in[2] : nullptr;  // 262080
    for (int i = 0; i < n_in; i++) {
        switch (in_sizes[i]) {
            case 113246208: src = (const float*)d_in[i]; break;
            case 72:        rot = (const float*)d_in[i]; break;
            case 262080:    ref = (const float*)d_in[i]; break;
            default: break; // gridF unused — recomputed analytically
        }
    }
    float* out = (float*)d_out;

    k_sample_cross<<<(NB * NY * NX + 255) / 256, 256>>>(src, rot, ref);
    k_ifft_y<<<NB * NX, 192>>>();
    k_c2r_x_top4<<<NB * NY, 192>>>();
    k_final<<<NB, 192>>>(out);
}